// round 3
// baseline (speedup 1.0000x reference)
#include <cuda_runtime.h>
#include <cstdint>
#include <cstddef>

// ---------------------------------------------------------------------------
// MSRResNetKPN forward, fp32 direct conv on packed fma.rn.f32x2 (FFMA2).
// B=4, H=W=256, 3x3 SAME convs (cross-correlation, XLA OIHW).
// v2: SLAB=8 / 2-row register tile (reg slack for LDS pipelining),
//     pre-shifted pixel pairs in smem, pre-packed (w,w) weights in global.
// ---------------------------------------------------------------------------

#define ACT_NONE  0
#define ACT_RELU  1
#define ACT_LRELU 2

static constexpr int Hh = 256;
static constexpr int Ww = 256;
static constexpr int Bb = 4;
static constexpr size_t HW = (size_t)Hh * Ww;   // 65536

typedef unsigned long long u64;

// ---- scratch (static __device__ arrays: allocation-free) ----
__device__ float g_fea1 [Bb * 64  * HW];
__device__ float g_fea  [Bb * 64  * HW];
__device__ float g_tmp  [Bb * 64  * HW];
__device__ float g_feat [Bb * 128 * HW];
__device__ float g_core [Bb * 75  * HW];
__device__ float g_resid[Bb * 3   * HW];

// packed weights: [layer][ic][ocp][10] u64, value = (w,w)
__device__ u64 g_wpk_trunk[32 * 64 * 64 * 10];
__device__ u64 g_wpk_first[3 * 64 * 10];
__device__ u64 g_wpk_c1   [128 * 80 * 10];
__device__ u64 g_wpk_c2a  [128 * 64 * 10];
__device__ u64 g_wpk_c2b  [64 * 8 * 10];
__device__ u64 g_wpk_c3a  [3 * 64 * 10];
__device__ u64 g_wpk_c3b  [64 * 64 * 10];
__device__ u64 g_wpk_c3c  [64 * 64 * 10];

// ---- f32x2 helpers ----
__device__ __forceinline__ u64 pk2(float lo, float hi) {
    u64 r;
    asm("mov.b64 %0, {%1, %2};" : "=l"(r) : "f"(lo), "f"(hi));
    return r;
}
__device__ __forceinline__ void upk2(u64 v, float& lo, float& hi) {
    asm("mov.b64 {%0, %1}, %2;" : "=f"(lo), "=f"(hi) : "l"(v));
}
__device__ __forceinline__ u64 f2fma(u64 a, u64 b, u64 c) {
    u64 d;
    asm("fma.rn.f32x2 %0, %1, %2, %3;" : "=l"(d) : "l"(a), "l"(b), "l"(c));
    return d;
}

// ---------------------------------------------------------------------------
// Weight pack: src OIHW [nL][OC][IC][3][3] f32 -> dst [nL][IC][OCP][10] u64
// dst[k] = (w,w); k==9 and oc>=OC zero-filled.
// ---------------------------------------------------------------------------
__global__ void pack_weights(const float* __restrict__ src, u64* __restrict__ dst,
                             int OC, int IC, int OCP, long total) {
    long idx = (long)blockIdx.x * blockDim.x + threadIdx.x;
    if (idx >= total) return;
    int k = (int)(idx % 10);
    long t = idx / 10;
    int oc = (int)(t % OCP);
    t /= OCP;
    int ic = (int)(t % IC);
    long l = t / IC;
    float w = 0.f;
    if (k < 9 && oc < OC)
        w = src[((l * OC + oc) * IC + ic) * 9 + k];
    unsigned u = __float_as_uint(w);
    dst[idx] = ((u64)u << 32) | (u64)u;
}

// ---------------------------------------------------------------------------
// Direct 3x3 conv. Output tile: 32 cols x 4 rows x OCP channels per block.
// Block (16,2,8): tx = pair-col (32 px), ty = row-pair, tz = 8-wide oc slab.
// Thread: 2 rows x 1 pixel-pair x SLAB oc.  Warp has uniform tz -> all weight
// LDS are broadcasts.
// ---------------------------------------------------------------------------
template <int IC, int OC, int OCP, int ACT, bool ACCUM>
__global__ void __launch_bounds__(256, 2)
conv3x3(const float* __restrict__ in, const u64* __restrict__ wp,
        const float* __restrict__ bias, float* __restrict__ out, int oct) {
    constexpr int ICS  = (IC % 4 == 0) ? 4 : IC;
    constexpr int NSTG = IC / ICS;
    constexpr int SLAB = OCP / 8;

    // s_p[ch][j][c] = ( in[y0-1+j][x0-1+c], in[y0-1+j][x0+c] )
    __shared__ u64 s_p[ICS][6][34];
    __shared__ __align__(16) u64 s_w[ICS][OCP][10];

    const int tx = threadIdx.x;            // 0..15
    const int ty = threadIdx.y;            // 0..1
    const int tz = threadIdx.z;            // 0..7
    const int tid = tx + (ty << 4) + (tz << 5);
    const int b  = blockIdx.z;
    const int x0 = blockIdx.x * 32;
    const int y0 = blockIdx.y * 4;
    const int oc0 = tz * SLAB;

    u64 acc[SLAB][2];
#pragma unroll
    for (int o = 0; o < SLAB; ++o) {
        float bv = 0.f;
        if (!(OCP > OC) || (oc0 + o) < OC) bv = bias[oc0 + o];
        acc[o][0] = pk2(bv, bv);
        acc[o][1] = acc[o][0];
    }

#pragma unroll 1
    for (int s = 0; s < NSTG; ++s) {
        const int ic0 = s * ICS;
        if (s) __syncthreads();

        // --- stage pre-shifted input pairs ---
        constexpr int E = ICS * 6 * 34;
        for (int e = tid; e < E; e += 256) {
            int c  = e % 34;
            int t  = e / 34;
            int j  = t % 6;
            int ch = t / 6;
            int gy = y0 - 1 + j;
            float lo = 0.f, hi = 0.f;
            if ((unsigned)gy < 256u) {
                const float* base =
                    in + (((size_t)b * IC + ic0 + ch) * Hh + gy) * Ww;
                int xl = x0 - 1 + c;
                int xh = x0 + c;
                if ((unsigned)xl < 256u) lo = __ldg(base + xl);
                if ((unsigned)xh < 256u) hi = __ldg(base + xh);
            }
            s_p[ch][j][c] = pk2(lo, hi);
        }
        // --- stage packed weights (straight copy) ---
        {
            constexpr int W2 = ICS * OCP * 10 / 2;
            const ulonglong2* src =
                reinterpret_cast<const ulonglong2*>(wp + (size_t)ic0 * OCP * 10);
            ulonglong2* dst = reinterpret_cast<ulonglong2*>(&s_w[0][0][0]);
            for (int i = tid; i < W2; i += 256) dst[i] = src[i];
        }
        __syncthreads();

#pragma unroll 2
        for (int ch = 0; ch < ICS; ++ch) {
            u64 p[4][3];
#pragma unroll
            for (int jj = 0; jj < 4; ++jj)
#pragma unroll
                for (int kj = 0; kj < 3; ++kj)
                    p[jj][kj] = s_p[ch][2 * ty + jj][2 * tx + kj];

#pragma unroll
            for (int o = 0; o < SLAB; ++o) {
                const ulonglong2* wv =
                    reinterpret_cast<const ulonglong2*>(&s_w[ch][oc0 + o][0]);
                ulonglong2 wa = wv[0], wb = wv[1], wc = wv[2], wd = wv[3];
                u64 w8 = wv[4].x;
                acc[o][0] = f2fma(p[0][0], wa.x, acc[o][0]);
                acc[o][1] = f2fma(p[1][0], wa.x, acc[o][1]);
                acc[o][0] = f2fma(p[0][1], wa.y, acc[o][0]);
                acc[o][1] = f2fma(p[1][1], wa.y, acc[o][1]);
                acc[o][0] = f2fma(p[0][2], wb.x, acc[o][0]);
                acc[o][1] = f2fma(p[1][2], wb.x, acc[o][1]);
                acc[o][0] = f2fma(p[1][0], wb.y, acc[o][0]);
                acc[o][1] = f2fma(p[2][0], wb.y, acc[o][1]);
                acc[o][0] = f2fma(p[1][1], wc.x, acc[o][0]);
                acc[o][1] = f2fma(p[2][1], wc.x, acc[o][1]);
                acc[o][0] = f2fma(p[1][2], wc.y, acc[o][0]);
                acc[o][1] = f2fma(p[2][2], wc.y, acc[o][1]);
                acc[o][0] = f2fma(p[2][0], wd.x, acc[o][0]);
                acc[o][1] = f2fma(p[3][0], wd.x, acc[o][1]);
                acc[o][0] = f2fma(p[2][1], wd.y, acc[o][0]);
                acc[o][1] = f2fma(p[3][1], wd.y, acc[o][1]);
                acc[o][0] = f2fma(p[2][2], w8, acc[o][0]);
                acc[o][1] = f2fma(p[3][2], w8, acc[o][1]);
            }
        }
    }

    // --- store / accumulate ---
#pragma unroll
    for (int o = 0; o < SLAB; ++o) {
        int oc = oc0 + o;
        if ((OCP > OC) && oc >= OC) continue;
#pragma unroll
        for (int r = 0; r < 2; ++r) {
            float lo, hi;
            upk2(acc[o][r], lo, hi);
            if (ACT == ACT_RELU) {
                lo = fmaxf(lo, 0.f);
                hi = fmaxf(hi, 0.f);
            } else if (ACT == ACT_LRELU) {
                lo = lo > 0.f ? lo : 0.1f * lo;
                hi = hi > 0.f ? hi : 0.1f * hi;
            }
            size_t oi = (((size_t)b * oct + oc) * Hh + (y0 + 2 * ty + r)) * Ww +
                        (x0 + 2 * tx);
            float2* po = reinterpret_cast<float2*>(out + oi);
            if (ACCUM) {
                float2 cur = *po;
                cur.x += lo;
                cur.y += hi;
                *po = cur;
            } else {
                float2 vv;
                vv.x = lo;
                vv.y = hi;
                *po = vv;
            }
        }
    }
}

// fea = fea1 (vectorized copy)
__global__ void copy4_kernel(const float4* __restrict__ src,
                             float4* __restrict__ dst, int n4) {
    int i = blockIdx.x * blockDim.x + threadIdx.x;
    if (i < n4) dst[i] = src[i];
}

// feat[:, 64:128] = fea + fea1
__global__ void add_feat_kernel(const float4* __restrict__ fea,
                                const float4* __restrict__ fea1,
                                float4* __restrict__ feat) {
    int i = blockIdx.x * blockDim.x + threadIdx.x;
    const int per_b = (int)(64 * HW / 4);
    if (i >= Bb * per_b) return;
    int b = i / per_b;
    int r = i - b * per_b;
    float4 a = fea[(size_t)b * per_b + r];
    float4 c = fea1[(size_t)b * per_b + r];
    float4 o;
    o.x = a.x + c.x; o.y = a.y + c.y; o.z = a.z + c.z; o.w = a.w + c.w;
    feat[((size_t)b * 128 + 64) * (HW / 4) + r] = o;
}

// out[b,c,h,w] = sum_{5x5} x[b,c,h+ki-2,w+kj-2]*core[b,c*25+k,h,w] + resid
__global__ void kpn_kernel(const float* __restrict__ x,
                           const float* __restrict__ core,
                           const float* __restrict__ resid,
                           float* __restrict__ out) {
    int idx = blockIdx.x * blockDim.x + threadIdx.x;
    const int n = Bb * 3 * (int)HW;
    if (idx >= n) return;
    int w = idx & 255;
    int h = (idx >> 8) & 255;
    int c = (idx >> 16) % 3;
    int b = idx / (3 * (int)HW);

    float s = resid[idx];
    size_t cb = (((size_t)b * 75 + (size_t)c * 25) * Hh + h) * Ww + w;
    size_t xb = ((size_t)b * 3 + c) * HW;
#pragma unroll
    for (int ki = 0; ki < 5; ++ki) {
        int gy = h + ki - 2;
        bool oky = (unsigned)gy < 256u;
#pragma unroll
        for (int kj = 0; kj < 5; ++kj) {
            int gx = w + kj - 2;
            float xv = 0.f;
            if (oky && (unsigned)gx < 256u)
                xv = x[xb + (size_t)gy * Ww + gx];
            s += xv * core[cb + (size_t)(ki * 5 + kj) * HW];
        }
    }
    out[idx] = s;
}

// ---------------------------------------------------------------------------
static void launch_pack(const float* src, u64* dst, int OC, int IC, int OCP,
                        int nL) {
    long total = (long)nL * IC * OCP * 10;
    int blocks = (int)((total + 255) / 256);
    pack_weights<<<blocks, 256>>>(src, dst, OC, IC, OCP, total);
}

extern "C" void kernel_launch(void* const* d_in, const int* in_sizes, int n_in,
                              void* d_out, int out_size) {
    const float* x       = (const float*)d_in[0];
    const float* w_first = (const float*)d_in[1];
    const float* b_first = (const float*)d_in[2];
    const float* w_trunk = (const float*)d_in[3];
    const float* b_trunk = (const float*)d_in[4];
    const float* c1_w    = (const float*)d_in[5];
    const float* c1_b    = (const float*)d_in[6];
    const float* c2_w1   = (const float*)d_in[7];
    const float* c2_b1   = (const float*)d_in[8];
    const float* c2_w2   = (const float*)d_in[9];
    const float* c2_b2   = (const float*)d_in[10];
    const float* c3_w1   = (const float*)d_in[11];
    const float* c3_b1   = (const float*)d_in[12];
    const float* c3_w2   = (const float*)d_in[13];
    const float* c3_b2   = (const float*)d_in[14];
    const float* c3_w3   = (const float*)d_in[15];
    const float* c3_b3   = (const float*)d_in[16];

    float *fea1, *fea, *tmp, *feat, *core, *resid;
    u64 *wtrunk, *wfirst, *wc1, *wc2a, *wc2b, *wc3a, *wc3b, *wc3c;
    cudaGetSymbolAddress((void**)&fea1,  g_fea1);
    cudaGetSymbolAddress((void**)&fea,   g_fea);
    cudaGetSymbolAddress((void**)&tmp,   g_tmp);
    cudaGetSymbolAddress((void**)&feat,  g_feat);
    cudaGetSymbolAddress((void**)&core,  g_core);
    cudaGetSymbolAddress((void**)&resid, g_resid);
    cudaGetSymbolAddress((void**)&wtrunk, g_wpk_trunk);
    cudaGetSymbolAddress((void**)&wfirst, g_wpk_first);
    cudaGetSymbolAddress((void**)&wc1,    g_wpk_c1);
    cudaGetSymbolAddress((void**)&wc2a,   g_wpk_c2a);
    cudaGetSymbolAddress((void**)&wc2b,   g_wpk_c2b);
    cudaGetSymbolAddress((void**)&wc3a,   g_wpk_c3a);
    cudaGetSymbolAddress((void**)&wc3b,   g_wpk_c3b);
    cudaGetSymbolAddress((void**)&wc3c,   g_wpk_c3c);

    // --- pack all weights ---
    launch_pack(w_trunk, wtrunk, 64, 64, 64, 32);
    launch_pack(w_first, wfirst, 64, 3, 64, 1);
    launch_pack(c1_w,    wc1,    75, 128, 80, 1);
    launch_pack(c2_w1,   wc2a,   64, 128, 64, 1);
    launch_pack(c2_w2,   wc2b,   3, 64, 8, 1);
    launch_pack(c3_w1,   wc3a,   64, 3, 64, 1);
    launch_pack(c3_w2,   wc3b,   64, 64, 64, 1);
    launch_pack(c3_w3,   wc3c,   64, 64, 64, 1);

    const dim3 grid(Ww / 32, Hh / 4, Bb);   // (8, 64, 4)
    const dim3 blk(16, 2, 8);

    // 1) fea1 = lrelu(conv_first(x))
    conv3x3<3, 64, 64, ACT_LRELU, false><<<grid, blk>>>(x, wfirst, b_first,
                                                        fea1, 64);
    // 2) fea = fea1
    {
        int n4 = (int)(Bb * 64 * HW / 4);
        copy4_kernel<<<(n4 + 255) / 256, 256>>>((const float4*)fea1,
                                                (float4*)fea, n4);
    }
    // 3) 16 residual blocks
    for (int i = 0; i < 16; ++i) {
        const u64* w1 = wtrunk + (size_t)(2 * i) * 64 * 64 * 10;
        const u64* w2 = wtrunk + (size_t)(2 * i + 1) * 64 * 64 * 10;
        const float* b1 = b_trunk + (size_t)(2 * i) * 64;
        const float* b2 = b_trunk + (size_t)(2 * i + 1) * 64;
        conv3x3<64, 64, 64, ACT_RELU, false><<<grid, blk>>>(fea, w1, b1, tmp,
                                                            64);
        conv3x3<64, 64, 64, ACT_NONE, true><<<grid, blk>>>(tmp, w2, b2, fea,
                                                           64);
    }
    // 4) feat[:,64:] = fea + fea1
    {
        int n4 = (int)(Bb * 64 * HW / 4);
        add_feat_kernel<<<(n4 + 255) / 256, 256>>>(
            (const float4*)fea, (const float4*)fea1, (float4*)feat);
    }
    // 5) c3 branch -> feat[:, :64]
    conv3x3<3, 64, 64, ACT_RELU, false><<<grid, blk>>>(x, wc3a, c3_b1, tmp, 64);
    conv3x3<64, 64, 64, ACT_RELU, false><<<grid, blk>>>(tmp, wc3b, c3_b2, fea1,
                                                        64);
    conv3x3<64, 64, 64, ACT_NONE, false><<<grid, blk>>>(fea1, wc3c, c3_b3,
                                                        feat, 128);
    // 6) residual branch
    conv3x3<128, 64, 64, ACT_RELU, false><<<grid, blk>>>(feat, wc2a, c2_b1,
                                                         tmp, 64);
    conv3x3<64, 3, 8, ACT_NONE, false><<<grid, blk>>>(tmp, wc2b, c2_b2, resid,
                                                      3);
    // 7) core = conv1(feat)
    conv3x3<128, 75, 80, ACT_NONE, false><<<grid, blk>>>(feat, wc1, c1_b, core,
                                                         75);
    // 8) KPN gather + residual
    {
        int n = Bb * 3 * (int)HW;
        kpn_kernel<<<(n + 255) / 256, 256>>>(x, core, resid, (float*)d_out);
    }
    (void)in_sizes; (void)n_in; (void)out_size;
}

// round 4
// speedup vs baseline: 1.0021x; 1.0021x over previous
#include <cuda_runtime.h>
#include <cstdint>
#include <cstddef>

// ---------------------------------------------------------------------------
// MSRResNetKPN forward, fp32 direct conv on packed fma.rn.f32x2 (FFMA2).
// B=4, H=W=256, 3x3 SAME convs (cross-correlation, XLA OIHW).
// v2: SLAB=8 / 2-row register tile (reg slack for LDS pipelining),
//     pre-shifted pixel pairs in smem, pre-packed (w,w) weights in global.
// ---------------------------------------------------------------------------

#define ACT_NONE  0
#define ACT_RELU  1
#define ACT_LRELU 2

static constexpr int Hh = 256;
static constexpr int Ww = 256;
static constexpr int Bb = 4;
static constexpr size_t HW = (size_t)Hh * Ww;   // 65536

typedef unsigned long long u64;

// ---- scratch (static __device__ arrays: allocation-free) ----
__device__ float g_fea1 [Bb * 64  * HW];
__device__ float g_fea  [Bb * 64  * HW];
__device__ float g_tmp  [Bb * 64  * HW];
__device__ float g_feat [Bb * 128 * HW];
__device__ float g_core [Bb * 75  * HW];
__device__ float g_resid[Bb * 3   * HW];

// packed weights: [layer][ic][ocp][10] u64, value = (w,w)
__device__ u64 g_wpk_trunk[32 * 64 * 64 * 10];
__device__ u64 g_wpk_first[3 * 64 * 10];
__device__ u64 g_wpk_c1   [128 * 80 * 10];
__device__ u64 g_wpk_c2a  [128 * 64 * 10];
__device__ u64 g_wpk_c2b  [64 * 8 * 10];
__device__ u64 g_wpk_c3a  [3 * 64 * 10];
__device__ u64 g_wpk_c3b  [64 * 64 * 10];
__device__ u64 g_wpk_c3c  [64 * 64 * 10];

// ---- f32x2 helpers ----
__device__ __forceinline__ u64 pk2(float lo, float hi) {
    u64 r;
    asm("mov.b64 %0, {%1, %2};" : "=l"(r) : "f"(lo), "f"(hi));
    return r;
}
__device__ __forceinline__ void upk2(u64 v, float& lo, float& hi) {
    asm("mov.b64 {%0, %1}, %2;" : "=f"(lo), "=f"(hi) : "l"(v));
}
__device__ __forceinline__ u64 f2fma(u64 a, u64 b, u64 c) {
    u64 d;
    asm("fma.rn.f32x2 %0, %1, %2, %3;" : "=l"(d) : "l"(a), "l"(b), "l"(c));
    return d;
}

// ---------------------------------------------------------------------------
// Weight pack: src OIHW [nL][OC][IC][3][3] f32 -> dst [nL][IC][OCP][10] u64
// dst[k] = (w,w); k==9 and oc>=OC zero-filled.
// ---------------------------------------------------------------------------
__global__ void pack_weights(const float* __restrict__ src, u64* __restrict__ dst,
                             int OC, int IC, int OCP, long total) {
    long idx = (long)blockIdx.x * blockDim.x + threadIdx.x;
    if (idx >= total) return;
    int k = (int)(idx % 10);
    long t = idx / 10;
    int oc = (int)(t % OCP);
    t /= OCP;
    int ic = (int)(t % IC);
    long l = t / IC;
    float w = 0.f;
    if (k < 9 && oc < OC)
        w = src[((l * OC + oc) * IC + ic) * 9 + k];
    unsigned u = __float_as_uint(w);
    dst[idx] = ((u64)u << 32) | (u64)u;
}

// ---------------------------------------------------------------------------
// Direct 3x3 conv. Output tile: 32 cols x 4 rows x OCP channels per block.
// Block (16,2,8): tx = pair-col (32 px), ty = row-pair, tz = 8-wide oc slab.
// Thread: 2 rows x 1 pixel-pair x SLAB oc.  Warp has uniform tz -> all weight
// LDS are broadcasts.
// ---------------------------------------------------------------------------
template <int IC, int OC, int OCP, int ACT, bool ACCUM>
__global__ void __launch_bounds__(256, 2)
conv3x3(const float* __restrict__ in, const u64* __restrict__ wp,
        const float* __restrict__ bias, float* __restrict__ out, int oct) {
    constexpr int ICS  = (IC % 4 == 0) ? 4 : IC;
    constexpr int NSTG = IC / ICS;
    constexpr int SLAB = OCP / 8;

    // s_p[ch][j][c] = ( in[y0-1+j][x0-1+c], in[y0-1+j][x0+c] )
    __shared__ u64 s_p[ICS][6][34];
    __shared__ __align__(16) u64 s_w[ICS][OCP][10];

    const int tx = threadIdx.x;            // 0..15
    const int ty = threadIdx.y;            // 0..1
    const int tz = threadIdx.z;            // 0..7
    const int tid = tx + (ty << 4) + (tz << 5);
    const int b  = blockIdx.z;
    const int x0 = blockIdx.x * 32;
    const int y0 = blockIdx.y * 4;
    const int oc0 = tz * SLAB;

    u64 acc[SLAB][2];
#pragma unroll
    for (int o = 0; o < SLAB; ++o) {
        float bv = 0.f;
        if (!(OCP > OC) || (oc0 + o) < OC) bv = bias[oc0 + o];
        acc[o][0] = pk2(bv, bv);
        acc[o][1] = acc[o][0];
    }

#pragma unroll 1
    for (int s = 0; s < NSTG; ++s) {
        const int ic0 = s * ICS;
        if (s) __syncthreads();

        // --- stage pre-shifted input pairs ---
        constexpr int E = ICS * 6 * 34;
        for (int e = tid; e < E; e += 256) {
            int c  = e % 34;
            int t  = e / 34;
            int j  = t % 6;
            int ch = t / 6;
            int gy = y0 - 1 + j;
            float lo = 0.f, hi = 0.f;
            if ((unsigned)gy < 256u) {
                const float* base =
                    in + (((size_t)b * IC + ic0 + ch) * Hh + gy) * Ww;
                int xl = x0 - 1 + c;
                int xh = x0 + c;
                if ((unsigned)xl < 256u) lo = __ldg(base + xl);
                if ((unsigned)xh < 256u) hi = __ldg(base + xh);
            }
            s_p[ch][j][c] = pk2(lo, hi);
        }
        // --- stage packed weights (straight copy) ---
        {
            constexpr int W2 = ICS * OCP * 10 / 2;
            const ulonglong2* src =
                reinterpret_cast<const ulonglong2*>(wp + (size_t)ic0 * OCP * 10);
            ulonglong2* dst = reinterpret_cast<ulonglong2*>(&s_w[0][0][0]);
            for (int i = tid; i < W2; i += 256) dst[i] = src[i];
        }
        __syncthreads();

#pragma unroll 2
        for (int ch = 0; ch < ICS; ++ch) {
            u64 p[4][3];
#pragma unroll
            for (int jj = 0; jj < 4; ++jj)
#pragma unroll
                for (int kj = 0; kj < 3; ++kj)
                    p[jj][kj] = s_p[ch][2 * ty + jj][2 * tx + kj];

#pragma unroll
            for (int o = 0; o < SLAB; ++o) {
                const ulonglong2* wv =
                    reinterpret_cast<const ulonglong2*>(&s_w[ch][oc0 + o][0]);
                ulonglong2 wa = wv[0], wb = wv[1], wc = wv[2], wd = wv[3];
                u64 w8 = wv[4].x;
                acc[o][0] = f2fma(p[0][0], wa.x, acc[o][0]);
                acc[o][1] = f2fma(p[1][0], wa.x, acc[o][1]);
                acc[o][0] = f2fma(p[0][1], wa.y, acc[o][0]);
                acc[o][1] = f2fma(p[1][1], wa.y, acc[o][1]);
                acc[o][0] = f2fma(p[0][2], wb.x, acc[o][0]);
                acc[o][1] = f2fma(p[1][2], wb.x, acc[o][1]);
                acc[o][0] = f2fma(p[1][0], wb.y, acc[o][0]);
                acc[o][1] = f2fma(p[2][0], wb.y, acc[o][1]);
                acc[o][0] = f2fma(p[1][1], wc.x, acc[o][0]);
                acc[o][1] = f2fma(p[2][1], wc.x, acc[o][1]);
                acc[o][0] = f2fma(p[1][2], wc.y, acc[o][0]);
                acc[o][1] = f2fma(p[2][2], wc.y, acc[o][1]);
                acc[o][0] = f2fma(p[2][0], wd.x, acc[o][0]);
                acc[o][1] = f2fma(p[3][0], wd.x, acc[o][1]);
                acc[o][0] = f2fma(p[2][1], wd.y, acc[o][0]);
                acc[o][1] = f2fma(p[3][1], wd.y, acc[o][1]);
                acc[o][0] = f2fma(p[2][2], w8, acc[o][0]);
                acc[o][1] = f2fma(p[3][2], w8, acc[o][1]);
            }
        }
    }

    // --- store / accumulate ---
#pragma unroll
    for (int o = 0; o < SLAB; ++o) {
        int oc = oc0 + o;
        if ((OCP > OC) && oc >= OC) continue;
#pragma unroll
        for (int r = 0; r < 2; ++r) {
            float lo, hi;
            upk2(acc[o][r], lo, hi);
            if (ACT == ACT_RELU) {
                lo = fmaxf(lo, 0.f);
                hi = fmaxf(hi, 0.f);
            } else if (ACT == ACT_LRELU) {
                lo = lo > 0.f ? lo : 0.1f * lo;
                hi = hi > 0.f ? hi : 0.1f * hi;
            }
            size_t oi = (((size_t)b * oct + oc) * Hh + (y0 + 2 * ty + r)) * Ww +
                        (x0 + 2 * tx);
            float2* po = reinterpret_cast<float2*>(out + oi);
            if (ACCUM) {
                float2 cur = *po;
                cur.x += lo;
                cur.y += hi;
                *po = cur;
            } else {
                float2 vv;
                vv.x = lo;
                vv.y = hi;
                *po = vv;
            }
        }
    }
}

// fea = fea1 (vectorized copy)
__global__ void copy4_kernel(const float4* __restrict__ src,
                             float4* __restrict__ dst, int n4) {
    int i = blockIdx.x * blockDim.x + threadIdx.x;
    if (i < n4) dst[i] = src[i];
}

// feat[:, 64:128] = fea + fea1
__global__ void add_feat_kernel(const float4* __restrict__ fea,
                                const float4* __restrict__ fea1,
                                float4* __restrict__ feat) {
    int i = blockIdx.x * blockDim.x + threadIdx.x;
    const int per_b = (int)(64 * HW / 4);
    if (i >= Bb * per_b) return;
    int b = i / per_b;
    int r = i - b * per_b;
    float4 a = fea[(size_t)b * per_b + r];
    float4 c = fea1[(size_t)b * per_b + r];
    float4 o;
    o.x = a.x + c.x; o.y = a.y + c.y; o.z = a.z + c.z; o.w = a.w + c.w;
    feat[((size_t)b * 128 + 64) * (HW / 4) + r] = o;
}

// out[b,c,h,w] = sum_{5x5} x[b,c,h+ki-2,w+kj-2]*core[b,c*25+k,h,w] + resid
__global__ void kpn_kernel(const float* __restrict__ x,
                           const float* __restrict__ core,
                           const float* __restrict__ resid,
                           float* __restrict__ out) {
    int idx = blockIdx.x * blockDim.x + threadIdx.x;
    const int n = Bb * 3 * (int)HW;
    if (idx >= n) return;
    int w = idx & 255;
    int h = (idx >> 8) & 255;
    int c = (idx >> 16) % 3;
    int b = idx / (3 * (int)HW);

    float s = resid[idx];
    size_t cb = (((size_t)b * 75 + (size_t)c * 25) * Hh + h) * Ww + w;
    size_t xb = ((size_t)b * 3 + c) * HW;
#pragma unroll
    for (int ki = 0; ki < 5; ++ki) {
        int gy = h + ki - 2;
        bool oky = (unsigned)gy < 256u;
#pragma unroll
        for (int kj = 0; kj < 5; ++kj) {
            int gx = w + kj - 2;
            float xv = 0.f;
            if (oky && (unsigned)gx < 256u)
                xv = x[xb + (size_t)gy * Ww + gx];
            s += xv * core[cb + (size_t)(ki * 5 + kj) * HW];
        }
    }
    out[idx] = s;
}

// ---------------------------------------------------------------------------
static void launch_pack(const float* src, u64* dst, int OC, int IC, int OCP,
                        int nL) {
    long total = (long)nL * IC * OCP * 10;
    int blocks = (int)((total + 255) / 256);
    pack_weights<<<blocks, 256>>>(src, dst, OC, IC, OCP, total);
}

extern "C" void kernel_launch(void* const* d_in, const int* in_sizes, int n_in,
                              void* d_out, int out_size) {
    const float* x       = (const float*)d_in[0];
    const float* w_first = (const float*)d_in[1];
    const float* b_first = (const float*)d_in[2];
    const float* w_trunk = (const float*)d_in[3];
    const float* b_trunk = (const float*)d_in[4];
    const float* c1_w    = (const float*)d_in[5];
    const float* c1_b    = (const float*)d_in[6];
    const float* c2_w1   = (const float*)d_in[7];
    const float* c2_b1   = (const float*)d_in[8];
    const float* c2_w2   = (const float*)d_in[9];
    const float* c2_b2   = (const float*)d_in[10];
    const float* c3_w1   = (const float*)d_in[11];
    const float* c3_b1   = (const float*)d_in[12];
    const float* c3_w2   = (const float*)d_in[13];
    const float* c3_b2   = (const float*)d_in[14];
    const float* c3_w3   = (const float*)d_in[15];
    const float* c3_b3   = (const float*)d_in[16];

    float *fea1, *fea, *tmp, *feat, *core, *resid;
    u64 *wtrunk, *wfirst, *wc1, *wc2a, *wc2b, *wc3a, *wc3b, *wc3c;
    cudaGetSymbolAddress((void**)&fea1,  g_fea1);
    cudaGetSymbolAddress((void**)&fea,   g_fea);
    cudaGetSymbolAddress((void**)&tmp,   g_tmp);
    cudaGetSymbolAddress((void**)&feat,  g_feat);
    cudaGetSymbolAddress((void**)&core,  g_core);
    cudaGetSymbolAddress((void**)&resid, g_resid);
    cudaGetSymbolAddress((void**)&wtrunk, g_wpk_trunk);
    cudaGetSymbolAddress((void**)&wfirst, g_wpk_first);
    cudaGetSymbolAddress((void**)&wc1,    g_wpk_c1);
    cudaGetSymbolAddress((void**)&wc2a,   g_wpk_c2a);
    cudaGetSymbolAddress((void**)&wc2b,   g_wpk_c2b);
    cudaGetSymbolAddress((void**)&wc3a,   g_wpk_c3a);
    cudaGetSymbolAddress((void**)&wc3b,   g_wpk_c3b);
    cudaGetSymbolAddress((void**)&wc3c,   g_wpk_c3c);

    // --- pack all weights ---
    launch_pack(w_trunk, wtrunk, 64, 64, 64, 32);
    launch_pack(w_first, wfirst, 64, 3, 64, 1);
    launch_pack(c1_w,    wc1,    75, 128, 80, 1);
    launch_pack(c2_w1,   wc2a,   64, 128, 64, 1);
    launch_pack(c2_w2,   wc2b,   3, 64, 8, 1);
    launch_pack(c3_w1,   wc3a,   64, 3, 64, 1);
    launch_pack(c3_w2,   wc3b,   64, 64, 64, 1);
    launch_pack(c3_w3,   wc3c,   64, 64, 64, 1);

    const dim3 grid(Ww / 32, Hh / 4, Bb);   // (8, 64, 4)
    const dim3 blk(16, 2, 8);

    // 1) fea1 = lrelu(conv_first(x))
    conv3x3<3, 64, 64, ACT_LRELU, false><<<grid, blk>>>(x, wfirst, b_first,
                                                        fea1, 64);
    // 2) fea = fea1
    {
        int n4 = (int)(Bb * 64 * HW / 4);
        copy4_kernel<<<(n4 + 255) / 256, 256>>>((const float4*)fea1,
                                                (float4*)fea, n4);
    }
    // 3) 16 residual blocks
    for (int i = 0; i < 16; ++i) {
        const u64* w1 = wtrunk + (size_t)(2 * i) * 64 * 64 * 10;
        const u64* w2 = wtrunk + (size_t)(2 * i + 1) * 64 * 64 * 10;
        const float* b1 = b_trunk + (size_t)(2 * i) * 64;
        const float* b2 = b_trunk + (size_t)(2 * i + 1) * 64;
        conv3x3<64, 64, 64, ACT_RELU, false><<<grid, blk>>>(fea, w1, b1, tmp,
                                                            64);
        conv3x3<64, 64, 64, ACT_NONE, true><<<grid, blk>>>(tmp, w2, b2, fea,
                                                           64);
    }
    // 4) feat[:,64:] = fea + fea1
    {
        int n4 = (int)(Bb * 64 * HW / 4);
        add_feat_kernel<<<(n4 + 255) / 256, 256>>>(
            (const float4*)fea, (const float4*)fea1, (float4*)feat);
    }
    // 5) c3 branch -> feat[:, :64]
    conv3x3<3, 64, 64, ACT_RELU, false><<<grid, blk>>>(x, wc3a, c3_b1, tmp, 64);
    conv3x3<64, 64, 64, ACT_RELU, false><<<grid, blk>>>(tmp, wc3b, c3_b2, fea1,
                                                        64);
    conv3x3<64, 64, 64, ACT_NONE, false><<<grid, blk>>>(fea1, wc3c, c3_b3,
                                                        feat, 128);
    // 6) residual branch
    conv3x3<128, 64, 64, ACT_RELU, false><<<grid, blk>>>(feat, wc2a, c2_b1,
                                                         tmp, 64);
    conv3x3<64, 3, 8, ACT_NONE, false><<<grid, blk>>>(tmp, wc2b, c2_b2, resid,
                                                      3);
    // 7) core = conv1(feat)
    conv3x3<128, 75, 80, ACT_NONE, false><<<grid, blk>>>(feat, wc1, c1_b, core,
                                                         75);
    // 8) KPN gather + residual
    {
        int n = Bb * 3 * (int)HW;
        kpn_kernel<<<(n + 255) / 256, 256>>>(x, core, resid, (float*)d_out);
    }
    (void)in_sizes; (void)n_in; (void)out_size;
}